// round 1
// baseline (speedup 1.0000x reference)
#include <cuda_runtime.h>
#include <cuda_bf16.h>

#define H       128
#define NBR     10
#define AF      35
#define BF      40            // ATOM_FDIM + BOND_FDIM
#define N_ATOMS 100000
#define N_BONDS 220000
#define N_MESS  20000
#define N_MOLS  2000
#define MSG_ROWS (N_MESS + N_BONDS)
#define KA      164           // 128 (nei) + 35 (fatoms) + 1 pad
#define TM      64            // rows per block tile
#define TB      256           // threads per block

// ---- scratch (device globals: allocation-free kernel_launch) ----
__device__ float g_msgA[(size_t)MSG_ROWS * H];
__device__ float g_msgB[(size_t)MSG_ROWS * H];
__device__ float g_binput[(size_t)N_BONDS * H];
__device__ float g_atomh[(size_t)N_ATOMS * H];

// ---------------------------------------------------------------
// copy tree_message into the head of both message ping-pong bufs
__global__ void tree_copy_kernel(const float* __restrict__ tree) {
    int i = blockIdx.x * blockDim.x + threadIdx.x;
    int n4 = N_MESS * H / 4;
    if (i < n4) {
        float4 v = ((const float4*)tree)[i];
        ((float4*)g_msgA)[i] = v;
        ((float4*)g_msgB)[i] = v;
    }
}

// ---------------------------------------------------------------
// binput = fbonds @ W_i ; msgA graph part = relu(binput)
__global__ void binput_kernel(const float* __restrict__ fbonds,
                              const float* __restrict__ W_i) {
    extern __shared__ float sm[];
    float* Asm = sm;             // [TM][BF]
    float* Wsm = sm + TM * BF;   // [BF][H]
    int m0 = blockIdx.x * TM;
    int tid = threadIdx.x;
    int warp = tid >> 5, lane = tid & 31;

    for (int i = tid * 4; i < BF * H; i += TB * 4)
        *(float4*)&Wsm[i] = *(const float4*)&W_i[i];
    for (int i = tid; i < TM * BF; i += TB) {
        int r = i / BF, c = i % BF;
        int m = m0 + r;
        Asm[i] = (m < N_BONDS) ? fbonds[(size_t)m * BF + c] : 0.f;
    }
    __syncthreads();

    float acc[8][4];
#pragma unroll
    for (int i = 0; i < 8; i++)
#pragma unroll
        for (int j = 0; j < 4; j++) acc[i][j] = 0.f;
    int n0 = lane * 4;
#pragma unroll
    for (int kk = 0; kk < BF; kk += 4) {
        float4 b0 = *(float4*)&Wsm[(kk + 0) * H + n0];
        float4 b1 = *(float4*)&Wsm[(kk + 1) * H + n0];
        float4 b2 = *(float4*)&Wsm[(kk + 2) * H + n0];
        float4 b3 = *(float4*)&Wsm[(kk + 3) * H + n0];
#pragma unroll
        for (int i = 0; i < 8; i++) {
            float4 a = *(float4*)&Asm[(warp * 8 + i) * BF + kk];
            acc[i][0] += a.x * b0.x + a.y * b1.x + a.z * b2.x + a.w * b3.x;
            acc[i][1] += a.x * b0.y + a.y * b1.y + a.z * b2.y + a.w * b3.y;
            acc[i][2] += a.x * b0.z + a.y * b1.z + a.z * b2.z + a.w * b3.z;
            acc[i][3] += a.x * b0.w + a.y * b1.w + a.z * b2.w + a.w * b3.w;
        }
    }
    float* graphA = g_msgA + (size_t)N_MESS * H;
#pragma unroll
    for (int i = 0; i < 8; i++) {
        int m = m0 + warp * 8 + i;
        if (m < N_BONDS) {
            float4 v = make_float4(acc[i][0], acc[i][1], acc[i][2], acc[i][3]);
            *(float4*)&g_binput[(size_t)m * H + n0] = v;
            float4 r = make_float4(fmaxf(v.x, 0.f), fmaxf(v.y, 0.f),
                                   fmaxf(v.z, 0.f), fmaxf(v.w, 0.f));
            *(float4*)&graphA[(size_t)m * H + n0] = r;
        }
    }
}

// ---------------------------------------------------------------
// one depth iter: dst_graph = relu(binput + gathersum(src_msg)@W_h)
__global__ void bond_update_kernel(const float* __restrict__ src_msg,
                                   float* __restrict__ dst_graph,
                                   const int* __restrict__ bgraph,
                                   const float* __restrict__ W_h) {
    extern __shared__ float sm[];
    float* Asm = sm;            // [TM][H]
    float* Wsm = sm + TM * H;   // [H][H]
    int m0 = blockIdx.x * TM;
    int tid = threadIdx.x;
    int warp = tid >> 5, lane = tid & 31;

    for (int i = tid * 4; i < H * H; i += TB * 4)
        *(float4*)&Wsm[i] = *(const float4*)&W_h[i];

    // gather: warp handles 8 rows, lane handles cols [4*lane, 4*lane+4)
#pragma unroll
    for (int rr = 0; rr < 8; rr++) {
        int r = warp * 8 + rr;
        int m = m0 + r;
        float4 acc = make_float4(0.f, 0.f, 0.f, 0.f);
        if (m < N_BONDS) {
            const int* bg = &bgraph[m * NBR];
#pragma unroll
            for (int nb = 0; nb < NBR; nb++) {
                int idx = bg[nb];
                float4 v = *(const float4*)&src_msg[(size_t)idx * H + lane * 4];
                acc.x += v.x; acc.y += v.y; acc.z += v.z; acc.w += v.w;
            }
        }
        *(float4*)&Asm[r * H + lane * 4] = acc;
    }
    __syncthreads();

    float acc[8][4];
#pragma unroll
    for (int i = 0; i < 8; i++)
#pragma unroll
        for (int j = 0; j < 4; j++) acc[i][j] = 0.f;
    int n0 = lane * 4;
    for (int kk = 0; kk < H; kk += 4) {
        float4 b0 = *(float4*)&Wsm[(kk + 0) * H + n0];
        float4 b1 = *(float4*)&Wsm[(kk + 1) * H + n0];
        float4 b2 = *(float4*)&Wsm[(kk + 2) * H + n0];
        float4 b3 = *(float4*)&Wsm[(kk + 3) * H + n0];
#pragma unroll
        for (int i = 0; i < 8; i++) {
            float4 a = *(float4*)&Asm[(warp * 8 + i) * H + kk];
            acc[i][0] += a.x * b0.x + a.y * b1.x + a.z * b2.x + a.w * b3.x;
            acc[i][1] += a.x * b0.y + a.y * b1.y + a.z * b2.y + a.w * b3.y;
            acc[i][2] += a.x * b0.z + a.y * b1.z + a.z * b2.z + a.w * b3.z;
            acc[i][3] += a.x * b0.w + a.y * b1.w + a.z * b2.w + a.w * b3.w;
        }
    }
#pragma unroll
    for (int i = 0; i < 8; i++) {
        int m = m0 + warp * 8 + i;
        if (m < N_BONDS) {
            float4 bi = *(const float4*)&g_binput[(size_t)m * H + n0];
            float4 o = make_float4(fmaxf(bi.x + acc[i][0], 0.f),
                                   fmaxf(bi.y + acc[i][1], 0.f),
                                   fmaxf(bi.z + acc[i][2], 0.f),
                                   fmaxf(bi.w + acc[i][3], 0.f));
            *(float4*)&dst_graph[(size_t)m * H + n0] = o;
        }
    }
}

// ---------------------------------------------------------------
// atom_hiddens = relu([fatoms, gathersum(msg)] @ W_o + b_o)
// A layout: cols [0,128) = nei, [128,163) = fatoms, 163 = pad
// W rows reordered to match (W_o rows 35..162 first, then 0..34, then 0-row)
__global__ void atom_kernel(const float* __restrict__ src_msg,
                            const int* __restrict__ agraph,
                            const float* __restrict__ fatoms,
                            const float* __restrict__ W_o,
                            const float* __restrict__ b_o) {
    extern __shared__ float sm[];
    float* Asm = sm;             // [TM][KA]
    float* Wsm = sm + TM * KA;   // [KA][H]
    int m0 = blockIdx.x * TM;
    int tid = threadIdx.x;
    int warp = tid >> 5, lane = tid & 31;

    for (int i = tid * 4; i < KA * H; i += TB * 4) {
        int k = i >> 7;  // /H
        int n = i & (H - 1);
        float4 v;
        if (k < 128)       v = *(const float4*)&W_o[(size_t)(35 + k) * H + n];
        else if (k < 163)  v = *(const float4*)&W_o[(size_t)(k - 128) * H + n];
        else               v = make_float4(0.f, 0.f, 0.f, 0.f);
        *(float4*)&Wsm[i] = v;
    }

    // nei gather into A[:, 0:128)
#pragma unroll
    for (int rr = 0; rr < 8; rr++) {
        int r = warp * 8 + rr;
        int m = m0 + r;
        float4 acc = make_float4(0.f, 0.f, 0.f, 0.f);
        if (m < N_ATOMS) {
            const int* ag = &agraph[m * NBR];
#pragma unroll
            for (int nb = 0; nb < NBR; nb++) {
                int idx = ag[nb];
                float4 v = *(const float4*)&src_msg[(size_t)idx * H + lane * 4];
                acc.x += v.x; acc.y += v.y; acc.z += v.z; acc.w += v.w;
            }
        }
        *(float4*)&Asm[r * KA + lane * 4] = acc;
    }
    // fatoms into A[:, 128:163), pad col 163
    for (int i = tid; i < TM * AF; i += TB) {
        int r = i / AF, c = i % AF;
        int m = m0 + r;
        Asm[r * KA + 128 + c] = (m < N_ATOMS) ? fatoms[(size_t)m * AF + c] : 0.f;
    }
    if (tid < TM) Asm[tid * KA + 163] = 0.f;
    __syncthreads();

    float acc[8][4];
#pragma unroll
    for (int i = 0; i < 8; i++)
#pragma unroll
        for (int j = 0; j < 4; j++) acc[i][j] = 0.f;
    int n0 = lane * 4;
    for (int kk = 0; kk < KA; kk += 4) {
        float4 b0 = *(float4*)&Wsm[(kk + 0) * H + n0];
        float4 b1 = *(float4*)&Wsm[(kk + 1) * H + n0];
        float4 b2 = *(float4*)&Wsm[(kk + 2) * H + n0];
        float4 b3 = *(float4*)&Wsm[(kk + 3) * H + n0];
#pragma unroll
        for (int i = 0; i < 8; i++) {
            float4 a = *(float4*)&Asm[(warp * 8 + i) * KA + kk];
            acc[i][0] += a.x * b0.x + a.y * b1.x + a.z * b2.x + a.w * b3.x;
            acc[i][1] += a.x * b0.y + a.y * b1.y + a.z * b2.y + a.w * b3.y;
            acc[i][2] += a.x * b0.z + a.y * b1.z + a.z * b2.z + a.w * b3.z;
            acc[i][3] += a.x * b0.w + a.y * b1.w + a.z * b2.w + a.w * b3.w;
        }
    }
    float4 bo = *(const float4*)&b_o[n0];
#pragma unroll
    for (int i = 0; i < 8; i++) {
        int m = m0 + warp * 8 + i;
        if (m < N_ATOMS) {
            float4 o = make_float4(fmaxf(acc[i][0] + bo.x, 0.f),
                                   fmaxf(acc[i][1] + bo.y, 0.f),
                                   fmaxf(acc[i][2] + bo.z, 0.f),
                                   fmaxf(acc[i][3] + bo.w, 0.f));
            *(float4*)&g_atomh[(size_t)m * H + n0] = o;
        }
    }
}

// ---------------------------------------------------------------
// per-molecule mean pool (mol_ids sorted -> contiguous ranges)
__device__ __forceinline__ int lowerb(const int* __restrict__ a, int n, int key) {
    int lo = 0, hi = n;
    while (lo < hi) {
        int mid = (lo + hi) >> 1;
        if (a[mid] < key) lo = mid + 1; else hi = mid;
    }
    return lo;
}

__global__ void pool_kernel(const int* __restrict__ mol_ids,
                            float* __restrict__ out) {
    int mol = blockIdx.x;
    int tid = threadIdx.x;
    int lo = lowerb(mol_ids, N_ATOMS, mol);
    int hi = lowerb(mol_ids, N_ATOMS, mol + 1);
    float s = 0.f;
    for (int a = lo; a < hi; a++)
        s += g_atomh[(size_t)a * H + tid];
    int cnt = hi - lo;
    out[(size_t)mol * H + tid] = cnt ? s / (float)cnt : 0.f;
}

// ---------------------------------------------------------------
extern "C" void kernel_launch(void* const* d_in, const int* in_sizes, int n_in,
                              void* d_out, int out_size) {
    const float *fatoms = nullptr, *fbonds = nullptr, *tree = nullptr;
    const float *W_i = nullptr, *W_h = nullptr, *W_o = nullptr, *b_o = nullptr;
    const int *agraph = nullptr, *bgraph = nullptr, *mol_ids = nullptr;
    for (int i = 0; i < n_in; i++) {
        switch (in_sizes[i]) {
            case 3500000: fatoms  = (const float*)d_in[i]; break;   // 100000*35
            case 8800000: fbonds  = (const float*)d_in[i]; break;   // 220000*40
            case 2560000: tree    = (const float*)d_in[i]; break;   // 20000*128
            case 1000000: agraph  = (const int*)d_in[i];   break;   // 100000*10
            case 2200000: bgraph  = (const int*)d_in[i];   break;   // 220000*10
            case 100000:  mol_ids = (const int*)d_in[i];   break;
            case 5120:    W_i     = (const float*)d_in[i]; break;   // 40*128
            case 16384:   W_h     = (const float*)d_in[i]; break;   // 128*128
            case 20864:   W_o     = (const float*)d_in[i]; break;   // 163*128
            case 128:     b_o     = (const float*)d_in[i]; break;
        }
    }

    const int BIN_SMEM  = (TM * BF + BF * H) * 4;     // 30.75 KB
    const int BOND_SMEM = (TM * H + H * H) * 4;       // 96 KB
    const int ATOM_SMEM = (TM * KA + KA * H) * 4;     // ~123 KB
    cudaFuncSetAttribute(bond_update_kernel,
                         cudaFuncAttributeMaxDynamicSharedMemorySize, BOND_SMEM);
    cudaFuncSetAttribute(atom_kernel,
                         cudaFuncAttributeMaxDynamicSharedMemorySize, ATOM_SMEM);

    float *msgA, *msgB;
    cudaGetSymbolAddress((void**)&msgA, g_msgA);
    cudaGetSymbolAddress((void**)&msgB, g_msgB);

    int tc_blocks = (N_MESS * H / 4 + 255) / 256;
    tree_copy_kernel<<<tc_blocks, 256>>>(tree);

    int grid_b = (N_BONDS + TM - 1) / TM;
    binput_kernel<<<grid_b, TB, BIN_SMEM>>>(fbonds, W_i);

    float* src = msgA;
    float* dst = msgB;
    for (int it = 0; it < 5; it++) {   // DEPTH-1
        bond_update_kernel<<<grid_b, TB, BOND_SMEM>>>(
            src, dst + (size_t)N_MESS * H, bgraph, W_h);
        float* t = src; src = dst; dst = t;
    }
    // final message lives in `src`

    int grid_a = (N_ATOMS + TM - 1) / TM;
    atom_kernel<<<grid_a, TB, ATOM_SMEM>>>(src, agraph, fatoms, W_o, b_o);

    pool_kernel<<<N_MOLS, H>>>(mol_ids, (float*)d_out);
}